// round 17
// baseline (speedup 1.0000x reference)
#include <cuda_runtime.h>
#include <cuda_bf16.h>
#include <math.h>
#include <stdint.h>

#define EE   300
#define HH   256
#define G4   1024
#define H2   512
#define H8   2048
#define BB   64
#define LQ   64
#define LC   512

__device__ float g_qemb[(size_t)BB * LQ * EE];
__device__ float g_cemb[(size_t)BB * LC * EE];
__device__ float g_xw  [(size_t)2 * BB * LC * G4];
__device__ float g_xwq [(size_t)2 * BB * LQ * G4];
__device__ float g_qout[(size_t)BB * LQ * H2];
__device__ float g_cout[(size_t)BB * LC * H2];
__device__ float g_S   [(size_t)BB * LC * LQ];
__device__ float g_smax[(size_t)BB * LC];
__device__ float g_batt[(size_t)BB * LC];
__device__ float g_cw  [(size_t)BB * LC];
__device__ float g_qw  [(size_t)BB * LQ];
__device__ float g_c2q [(size_t)BB * LC * H2];
__device__ float g_q2c [(size_t)BB * H2];
__device__ float g_G   [(size_t)BB * LC * H8];
__device__ float g_M   [(size_t)BB * LC * H2];
__device__ float g_h   [(size_t)4 * HH * BB];
__device__ float g_wcvt[(size_t)2 * G4 * H8];
__device__ unsigned g_bar_cnt4[4] = {0, 0, 0, 0};
__device__ unsigned g_bar_gen4[4] = {0, 0, 0, 0};

__device__ __forceinline__ float sigmoidf_(float x) { return 1.f / (1.f + expf(-x)); }

__device__ __forceinline__ uint32_t f2tf32(float x)
{
    uint32_t r;
    asm("cvt.rna.tf32.f32 %0, %1;" : "=r"(r) : "f"(x));
    return r;
}
__device__ __forceinline__ float rtf(float x) { return __uint_as_float(f2tf32(x)); }

// Fence-lite grid barrier over a 32-block group (proxy-thread release/acquire).
__device__ __forceinline__ void grid_barrier_g(int grp, unsigned nb)
{
    __syncthreads();
    if (threadIdx.x == 0) {
        asm volatile("fence.acq_rel.gpu;" ::: "memory");
        unsigned g = *(volatile unsigned*)&g_bar_gen4[grp];
        if (atomicAdd(&g_bar_cnt4[grp], 1u) == nb - 1u) {
            g_bar_cnt4[grp] = 0;
            __threadfence();
            atomicAdd(&g_bar_gen4[grp], 1u);
        } else {
            while (*(volatile unsigned*)&g_bar_gen4[grp] == g) { }
        }
        asm volatile("fence.acq_rel.gpu;" ::: "memory");
    }
    __syncthreads();
}

__device__ __forceinline__ void cp16(uint32_t dst, const void* src)
{
    asm volatile("cp.async.cg.shared.global [%0], [%1], 16;" :: "r"(dst), "l"(src));
}
__device__ __forceinline__ uint32_t smem_u32(const void* p)
{
    uint32_t a;
    asm("{ .reg .u64 t; cvta.to.shared.u64 t, %1; cvt.u32.u64 %0, t; }" : "=r"(a) : "l"(p));
    return a;
}

// ---------------------------------------------------------------------------
__global__ void gather_emb(const int* __restrict__ tok, const float* __restrict__ emb,
                           float* __restrict__ out, int total)
{
    int i = blockIdx.x * blockDim.x + threadIdx.x;
    if (i >= total) return;
    int row = i / EE;
    int e   = i - row * EE;
    out[i] = rtf(emb[(size_t)tok[row] * EE + e]);
}

__global__ void cvt_tf32(const float* __restrict__ in, float* __restrict__ out, int n)
{
    int i = blockIdx.x * blockDim.x + threadIdx.x;
    if (i < n) out[i] = rtf(in[i]);
}

// ---------------------------------------------------------------------------
// tf32 mma.sync GEMM v5: CTA 128x128, 4 warps, warp 64x64, BK=32.
// 2-stage cp.async (73.7 KB smem -> 2 CTAs/SM) + single __syncthreads per
// k-tile; fill(kt+1) issued after sync, overlapping compute(kt).
// Stage (kt+1)&1 was consumed at iter kt-1; sync at kt joins all warps.
// ---------------------------------------------------------------------------
#define SROW 36
#define STILE (128 * SROW)
#define GSTAGE (2 * STILE)
#define GEMM_SMEM (2 * GSTAGE * (int)sizeof(float))   // 73728 B

__device__ __forceinline__ void fill_tile(uint32_t sA, uint32_t sB,
                                          const float* __restrict__ A,
                                          const float* __restrict__ B,
                                          int bm, int bn, int K, int k0, int tid)
{
#pragma unroll
    for (int i = 0; i < 8; ++i) {
        int idx = tid + i * 128;
        int row = idx >> 3, c4 = idx & 7;
        int k = k0 + c4 * 4;
        uint32_t da = sA + (row * SROW + c4 * 4) * 4;
        uint32_t db = sB + (row * SROW + c4 * 4) * 4;
        if (k + 4 <= K) {
            cp16(da, &A[(size_t)(bm + row) * K + k]);
            cp16(db, &B[(size_t)(bn + row) * K + k]);
        } else {
            asm volatile("st.shared.v4.b32 [%0], {%1,%1,%1,%1};" :: "r"(da), "r"(0) : "memory");
            asm volatile("st.shared.v4.b32 [%0], {%1,%1,%1,%1};" :: "r"(db), "r"(0) : "memory");
        }
    }
}

__global__ void __launch_bounds__(128)
gemm_tf32(const float* __restrict__ A, const float* __restrict__ B,
          const float* __restrict__ bias, float* __restrict__ C,
          int M, int N, int K)
{
    extern __shared__ float sh[];
    const int tid  = threadIdx.x;
    const int lane = tid & 31;
    const int warp = tid >> 5;
    const int g = lane >> 2, t = lane & 3;
    const int m0 = (warp & 1) * 64;
    const int n0 = (warp >> 1) * 64;
    const int bm = blockIdx.y * 128;
    const int bn = blockIdx.x * 128;
    const uint32_t sb = smem_u32(sh);

    float acc[4][8][4];
#pragma unroll
    for (int mi = 0; mi < 4; ++mi)
#pragma unroll
        for (int ni = 0; ni < 8; ++ni)
#pragma unroll
            for (int k = 0; k < 4; ++k) acc[mi][ni][k] = 0.f;

    const int nk = (K + 31) >> 5;
    const uint32_t stage_b = GSTAGE * 4;

    fill_tile(sb, sb + STILE * 4, A, B, bm, bn, K, 0, tid);
    asm volatile("cp.async.commit_group;" ::: "memory");

    for (int kt = 0; kt < nk; ++kt) {
        const int s = kt & 1;
        asm volatile("cp.async.wait_group 0;" ::: "memory");  // stage kt ready
        __syncthreads();                                      // all warps past kt-1
        if (kt + 1 < nk) {
            const int s2 = (kt + 1) & 1;
            fill_tile(sb + s2 * stage_b, sb + s2 * stage_b + STILE * 4,
                      A, B, bm, bn, K, (kt + 1) * 32, tid);
            asm volatile("cp.async.commit_group;" ::: "memory");
        }

        const float* Ab = sh + s * GSTAGE;
        const float* Bb = Ab + STILE;
#pragma unroll
        for (int kk = 0; kk < 32; kk += 8) {
            uint32_t af[4][4];
#pragma unroll
            for (int mi = 0; mi < 4; ++mi) {
                const float* ap = Ab + (m0 + mi * 16) * SROW + kk;
                af[mi][0] = __float_as_uint(ap[g * SROW + t]);
                af[mi][1] = __float_as_uint(ap[(g + 8) * SROW + t]);
                af[mi][2] = __float_as_uint(ap[g * SROW + t + 4]);
                af[mi][3] = __float_as_uint(ap[(g + 8) * SROW + t + 4]);
            }
            uint32_t bf[8][2];
#pragma unroll
            for (int ni = 0; ni < 8; ++ni) {
                const float* bp = Bb + (n0 + ni * 8) * SROW + kk;
                bf[ni][0] = __float_as_uint(bp[g * SROW + t]);
                bf[ni][1] = __float_as_uint(bp[g * SROW + t + 4]);
            }
#pragma unroll
            for (int mi = 0; mi < 4; ++mi)
#pragma unroll
                for (int ni = 0; ni < 8; ++ni)
                    asm volatile(
                        "mma.sync.aligned.m16n8k8.row.col.f32.tf32.tf32.f32 "
                        "{%0,%1,%2,%3}, {%4,%5,%6,%7}, {%8,%9}, {%0,%1,%2,%3};\n"
                        : "+f"(acc[mi][ni][0]), "+f"(acc[mi][ni][1]),
                          "+f"(acc[mi][ni][2]), "+f"(acc[mi][ni][3])
                        : "r"(af[mi][0]), "r"(af[mi][1]), "r"(af[mi][2]), "r"(af[mi][3]),
                          "r"(bf[ni][0]), "r"(bf[ni][1]));
        }
    }

#pragma unroll
    for (int mi = 0; mi < 4; ++mi) {
#pragma unroll
        for (int ni = 0; ni < 8; ++ni) {
            int row0 = bm + m0 + mi * 16 + g;
            int col  = bn + n0 + ni * 8 + t * 2;
            float2 bv = make_float2(0.f, 0.f);
            if (bias) bv = *(const float2*)&bias[col];
            *(float2*)&C[(size_t)row0 * N + col] =
                make_float2(acc[mi][ni][0] + bv.x, acc[mi][ni][1] + bv.y);
            *(float2*)&C[(size_t)(row0 + 8) * N + col] =
                make_float2(acc[mi][ni][2] + bv.x, acc[mi][ni][3] + bv.y);
        }
    }
}

// ---------------------------------------------------------------------------
// BiLSTM scan, tensor-core recurrence. Barrier group = blockIdx.x>>5 (32
// blocks = one direction chain). Whh converted to tf32 inline at wreg load.
// xW for step s+1 prefetched into registers before the barrier.
// ---------------------------------------------------------------------------
#define LPAD 72
#define SC_H   (HH * LPAD)
#define SC_XW  (SC_H + BB * 33)
#define SC_TOT (SC_XW + BB * 33)
#define SCAN_SMEM (SC_TOT * (int)sizeof(float))   // 90624 B

__global__ void __launch_bounds__(256)
lstm_scan2(const float* __restrict__ xW0, const float* __restrict__ Whh0,
           float* __restrict__ out0, int T0,
           const float* __restrict__ xW1, const float* __restrict__ Whh1,
           float* __restrict__ out1, int T1)
{
    extern __shared__ float sh[];
    float* h_sh  = sh;
    float* xw_sh = sh + SC_H;
    float* P_sh  = sh + SC_XW;

    const int tid  = threadIdx.x;
    const int lane = tid & 31;
    const int warp = tid >> 5;
    const int g = lane >> 2, t = lane & 3;
    const int nt  = warp >> 1;
    const int mtp = warp & 1;
    const int grp = blockIdx.x >> 6;          // data group
    const int bgr = blockIdx.x >> 5;          // barrier group (per dir)
    const int bid = blockIdx.x & 63;
    const int dir = bid >> 5;
    const int j0  = (bid & 31) * 8;

    const float* xWall = grp ? xW1 : xW0;
    const float* Whh   = grp ? Whh1 : Whh0;
    float*       outp  = grp ? out1 : out0;
    const int    T     = grp ? T1 : T0;

    float wreg[64];
    {
        const float* Wd = Whh + (size_t)dir * G4 * HH + (size_t)(nt * HH + j0 + g) * HH;
#pragma unroll
        for (int kt = 0; kt < 32; ++kt) {
            wreg[2 * kt]     = rtf(Wd[kt * 8 + t]);
            wreg[2 * kt + 1] = rtf(Wd[kt * 8 + t + 4]);
        }
    }

    const float* xWD = xWall + (size_t)dir * BB * T * G4;
    float*       hD  = g_h + (size_t)(grp * 2 + dir) * HH * BB;
    const int eb = tid & 63, eu = tid >> 6;
    float cst[2] = {0.f, 0.f};

    float4 xv0, xv1;
    {
        const int tt0 = dir ? (T - 1) : 0;
        const float* src = &xWD[((size_t)eb * T + tt0) * G4 + eu * HH + j0];
        xv0 = *(const float4*)src;
        xv1 = *(const float4*)(src + 4);
    }

    for (int s = 0; s < T; ++s) {
        const int tt = dir ? (T - 1 - s) : s;
        {
            float* d = &xw_sh[eb * 33 + eu * 8];
            d[0] = xv0.x; d[1] = xv0.y; d[2] = xv0.z; d[3] = xv0.w;
            d[4] = xv1.x; d[5] = xv1.y; d[6] = xv1.z; d[7] = xv1.w;
        }
        if (s > 0) {
            const float4* h4 = (const float4*)hD;
#pragma unroll
            for (int i = 0; i < 16; ++i) {
                int idx4 = tid + i * 256;
                int j = idx4 >> 4, b4 = (idx4 & 15) << 2;
                float4 v = __ldcg(h4 + idx4);
                *(float4*)&h_sh[j * LPAD + b4] = v;
            }
        }
        __syncthreads();

        float cf[2][4] = {{0.f, 0.f, 0.f, 0.f}, {0.f, 0.f, 0.f, 0.f}};
        if (s > 0) {
#pragma unroll
            for (int kt = 0; kt < 32; ++kt) {
                const float* hr0 = &h_sh[(kt * 8 + t) * LPAD];
                const float* hr1 = &h_sh[(kt * 8 + t + 4) * LPAD];
                uint32_t b0 = __float_as_uint(wreg[2 * kt]);
                uint32_t b1 = __float_as_uint(wreg[2 * kt + 1]);
#pragma unroll
                for (int p = 0; p < 2; ++p) {
                    int mb = mtp * 16 + p * 32;
                    uint32_t a0 = __float_as_uint(hr0[mb + g]);
                    uint32_t a1 = __float_as_uint(hr0[mb + g + 8]);
                    uint32_t a2 = __float_as_uint(hr1[mb + g]);
                    uint32_t a3 = __float_as_uint(hr1[mb + g + 8]);
                    asm volatile(
                        "mma.sync.aligned.m16n8k8.row.col.f32.tf32.tf32.f32 "
                        "{%0,%1,%2,%3}, {%4,%5,%6,%7}, {%8,%9}, {%0,%1,%2,%3};\n"
                        : "+f"(cf[p][0]), "+f"(cf[p][1]), "+f"(cf[p][2]), "+f"(cf[p][3])
                        : "r"(a0), "r"(a1), "r"(a2), "r"(a3), "r"(b0), "r"(b1));
                }
            }
        }
#pragma unroll
        for (int p = 0; p < 2; ++p) {
            int mb = mtp * 16 + p * 32;
            int cc = nt * 8 + 2 * t;
            P_sh[(mb + g) * 33 + cc]     = cf[p][0];
            P_sh[(mb + g) * 33 + cc + 1] = cf[p][1];
            P_sh[(mb + g + 8) * 33 + cc]     = cf[p][2];
            P_sh[(mb + g + 8) * 33 + cc + 1] = cf[p][3];
        }
        __syncthreads();

#pragma unroll
        for (int u = 0; u < 2; ++u) {
            int ju = eu + u * 4;
            const float* Pr = &P_sh[eb * 33];
            const float* Xr = &xw_sh[eb * 33];
            float pi = Pr[ju]      + Xr[ju];
            float pf = Pr[8 + ju]  + Xr[8 + ju];
            float pg = Pr[16 + ju] + Xr[16 + ju];
            float po = Pr[24 + ju] + Xr[24 + ju];
            float ig = sigmoidf_(pi);
            float fg = sigmoidf_(pf);
            float gg = tanhf(pg);
            float og = sigmoidf_(po);
            cst[u] = fg * cst[u] + ig * gg;
            float hh = og * tanhf(cst[u]);
            __stcg(&hD[(j0 + ju) * BB + eb], rtf(hh));
            outp[((size_t)eb * T + tt) * H2 + dir * HH + j0 + ju] = hh;
        }
        if (s + 1 < T) {
            {
                const int tn = dir ? (T - 2 - s) : (s + 1);
                const float* src = &xWD[((size_t)eb * T + tn) * G4 + eu * HH + j0];
                xv0 = *(const float4*)src;
                xv1 = *(const float4*)(src + 4);
            }
            grid_barrier_g(bgr, 32);
        }
    }
}

// ---------------------------------------------------------------------------
__global__ void rowdot(const float* __restrict__ A, const float* __restrict__ w,
                       const float* __restrict__ bias, float* __restrict__ out, int rows)
{
    int gw = (blockIdx.x * blockDim.x + threadIdx.x) >> 5;
    int lane = threadIdx.x & 31;
    if (gw >= rows) return;
    const float* row = A + (size_t)gw * H2;
    float s = 0.f;
#pragma unroll
    for (int i = 0; i < 16; ++i) s += row[lane + i * 32] * w[lane + i * 32];
#pragma unroll
    for (int off = 16; off; off >>= 1) s += __shfl_xor_sync(0xffffffffu, s, off);
    if (lane == 0) out[gw] = s + (bias ? bias[0] : 0.f);
}

__global__ void rowdot2(const float* __restrict__ A,
                        const float* __restrict__ w0, const float* __restrict__ b0,
                        const float* __restrict__ w1, const float* __restrict__ b1,
                        float* __restrict__ o0, float* __restrict__ o1, int rows)
{
    int gw = (blockIdx.x * blockDim.x + threadIdx.x) >> 5;
    int lane = threadIdx.x & 31;
    if (gw >= rows) return;
    const float* row = A + (size_t)gw * H2;
    float s0 = 0.f, s1 = 0.f;
#pragma unroll
    for (int i = 0; i < 16; ++i) {
        float v = row[lane + i * 32];
        s0 += v * w0[lane + i * 32];
        s1 += v * w1[lane + i * 32];
    }
#pragma unroll
    for (int off = 16; off; off >>= 1) {
        s0 += __shfl_xor_sync(0xffffffffu, s0, off);
        s1 += __shfl_xor_sync(0xffffffffu, s1, off);
    }
    if (lane == 0) {
        o0[gw] = s0 + b0[0];
        o1[gw] = s1 + b1[0];
    }
}

__global__ void __launch_bounds__(256)
attn_S(const float* __restrict__ c_out, const float* __restrict__ q_out,
       const float* __restrict__ sim_w, const float* __restrict__ sim_b,
       const float* __restrict__ cw, const float* __restrict__ qw,
       float* __restrict__ S)
{
    __shared__ float As[16][68];
    __shared__ float Bs[16][68];
    const int b = blockIdx.y, cc0 = blockIdx.x * 64;
    const float* A  = c_out + ((size_t)b * LC + cc0) * H2;
    const float* Bq = q_out + (size_t)b * LQ * H2;
    const float* wcq = sim_w + 2 * H2;
    const int tid = threadIdx.x;
    const int lr = tid >> 2, lk4 = (tid & 3) * 4;
    const int tx = tid & 15, ty = tid >> 4;
    float acc[4][4];
#pragma unroll
    for (int i = 0; i < 4; ++i)
#pragma unroll
        for (int j = 0; j < 4; ++j) acc[i][j] = 0.f;

    for (int k0 = 0; k0 < H2; k0 += 16) {
        float4 va = *(const float4*)&A[(size_t)lr * H2 + k0 + lk4];
        float4 wv = *(const float4*)&wcq[k0 + lk4];
        As[lk4 + 0][lr] = va.x * wv.x;
        As[lk4 + 1][lr] = va.y * wv.y;
        As[lk4 + 2][lr] = va.z * wv.z;
        As[lk4 + 3][lr] = va.w * wv.w;
        float4 vb = *(const float4*)&Bq[(size_t)lr * H2 + k0 + lk4];
        Bs[lk4 + 0][lr] = vb.x;
        Bs[lk4 + 1][lr] = vb.y;
        Bs[lk4 + 2][lr] = vb.z;
        Bs[lk4 + 3][lr] = vb.w;
        __syncthreads();
#pragma unroll
        for (int k = 0; k < 16; ++k) {
            float4 av = *(const float4*)&As[k][ty * 4];
            float4 bv = *(const float4*)&Bs[k][tx * 4];
            float am[4] = {av.x, av.y, av.z, av.w};
            float bn[4] = {bv.x, bv.y, bv.z, bv.w};
#pragma unroll
            for (int i = 0; i < 4; ++i)
#pragma unroll
                for (int j = 0; j < 4; ++j) acc[i][j] += am[i] * bn[j];
        }
        __syncthreads();
    }
    float sb = sim_b[0];
#pragma unroll
    for (int i = 0; i < 4; ++i) {
        int cc = cc0 + ty * 4 + i;
        float cwv = cw[b * LC + cc];
#pragma unroll
        for (int j = 0; j < 4; ++j) {
            int qq = tx * 4 + j;
            S[((size_t)b * LC + cc) * LQ + qq] = acc[i][j] + cwv + qw[b * LQ + qq] + sb;
        }
    }
}

__global__ void softmax64(float* __restrict__ S, float* __restrict__ smax, int rows)
{
    int gw = (blockIdx.x * blockDim.x + threadIdx.x) >> 5;
    int lane = threadIdx.x & 31;
    if (gw >= rows) return;
    float* row = S + (size_t)gw * LQ;
    float v0 = row[lane], v1 = row[lane + 32];
    float m = fmaxf(v0, v1);
#pragma unroll
    for (int off = 16; off; off >>= 1) m = fmaxf(m, __shfl_xor_sync(0xffffffffu, m, off));
    float e0 = expf(v0 - m), e1 = expf(v1 - m);
    float s = e0 + e1;
#pragma unroll
    for (int off = 16; off; off >>= 1) s += __shfl_xor_sync(0xffffffffu, s, off);
    float inv = 1.f / s;
    row[lane] = e0 * inv;
    row[lane + 32] = e1 * inv;
    if (lane == 0) smax[gw] = m;
}

__global__ void softmax512(const float* __restrict__ in, float* __restrict__ outv)
{
    __shared__ float red[16];
    int b = blockIdx.x, tid = threadIdx.x;
    float v = in[(size_t)b * LC + tid];
    float m = v;
#pragma unroll
    for (int off = 16; off; off >>= 1) m = fmaxf(m, __shfl_xor_sync(0xffffffffu, m, off));
    if ((tid & 31) == 0) red[tid >> 5] = m;
    __syncthreads();
    if (tid == 0) {
        float x = red[0];
        for (int i = 1; i < 16; ++i) x = fmaxf(x, red[i]);
        red[0] = x;
    }
    __syncthreads();
    m = red[0];
    __syncthreads();
    float e = expf(v - m);
    float s = e;
#pragma unroll
    for (int off = 16; off; off >>= 1) s += __shfl_xor_sync(0xffffffffu, s, off);
    if ((tid & 31) == 0) red[tid >> 5] = s;
    __syncthreads();
    if (tid == 0) {
        float x = 0.f;
        for (int i = 0; i < 16; ++i) x += red[i];
        red[0] = x;
    }
    __syncthreads();
    outv[(size_t)b * LC + tid] = e / red[0];
}

__global__ void __launch_bounds__(256)
attn_c2q(const float* __restrict__ a, const float* __restrict__ q_out,
         float* __restrict__ c2q)
{
    __shared__ float As[16][68];
    __shared__ float Bs[16][68];
    const int b = blockIdx.z, cc0 = blockIdx.y * 64, h0 = blockIdx.x * 64;
    const float* A = a + ((size_t)b * LC + cc0) * LQ;
    const float* B = q_out + (size_t)b * LQ * H2;
    const int tid = threadIdx.x;
    const int lr = tid >> 2, lk4 = (tid & 3) * 4;
    const int bk = tid >> 4, bn4 = (tid & 15) * 4;
    const int tx = tid & 15, ty = tid >> 4;
    float acc[4][4];
#pragma unroll
    for (int i = 0; i < 4; ++i)
#pragma unroll
        for (int j = 0; j < 4; ++j) acc[i][j] = 0.f;

    for (int k0 = 0; k0 < LQ; k0 += 16) {
        float4 va = *(const float4*)&A[(size_t)lr * LQ + k0 + lk4];
        As[lk4 + 0][lr] = va.x;
        As[lk4 + 1][lr] = va.y;
        As[lk4 + 2][lr] = va.z;
        As[lk4 + 3][lr] = va.w;
        float4 vb = *(const float4*)&B[(size_t)(k0 + bk) * H2 + h0 + bn4];
        *(float4*)&Bs[bk][bn4] = vb;
        __syncthreads();
#pragma unroll
        for (int k = 0; k < 16; ++k) {
            float4 av = *(const float4*)&As[k][ty * 4];
            float4 bv = *(const float4*)&Bs[k][tx * 4];
            float am[4] = {av.x, av.y, av.z, av.w};
            float bn[4] = {bv.x, bv.y, bv.z, bv.w};
#pragma unroll
            for (int i = 0; i < 4; ++i)
#pragma unroll
                for (int j = 0; j < 4; ++j) acc[i][j] += am[i] * bn[j];
        }
        __syncthreads();
    }
#pragma unroll
    for (int i = 0; i < 4; ++i)
#pragma unroll
        for (int j = 0; j < 4; ++j)
            c2q[((size_t)b * LC + cc0 + ty * 4 + i) * H2 + h0 + tx * 4 + j] = acc[i][j];
}

__global__ void attn_q2c(const float* __restrict__ batt, const float* __restrict__ c_out,
                         float* __restrict__ q2c)
{
    int b = blockIdx.y;
    int h = blockIdx.x * 128 + threadIdx.x;
    const float* C = c_out + (size_t)b * LC * H2;
    const float* w = batt + (size_t)b * LC;
    float acc = 0.f;
    for (int cc = 0; cc < LC; ++cc) acc += w[cc] * C[(size_t)cc * H2 + h];
    q2c[(size_t)b * H2 + h] = acc;
}

__global__ void build_G(const float* __restrict__ c_out, const float* __restrict__ c2q,
                        const float* __restrict__ q2c, float* __restrict__ G)
{
    size_t i = (size_t)blockIdx.x * blockDim.x + threadIdx.x;
    const size_t total = (size_t)BB * LC * (H2 / 4);
    if (i >= total) return;
    int h4 = (int)(i % (H2 / 4));
    size_t r = i / (H2 / 4);
    int b = (int)(r / LC);
    float4 co = ((const float4*)c_out)[r * (H2 / 4) + h4];
    float4 cq = ((const float4*)c2q)[r * (H2 / 4) + h4];
    float4 q2 = ((const float4*)q2c)[(size_t)b * (H2 / 4) + h4];
    float4* Gr = (float4*)(G + r * H8);
    Gr[h4] = make_float4(rtf(co.x), rtf(co.y), rtf(co.z), rtf(co.w));
    Gr[(H2 / 4) + h4] = make_float4(rtf(cq.x), rtf(cq.y), rtf(cq.z), rtf(cq.w));
    Gr[2 * (H2 / 4) + h4] = make_float4(rtf(co.x * cq.x), rtf(co.y * cq.y),
                                        rtf(co.z * cq.z), rtf(co.w * cq.w));
    Gr[3 * (H2 / 4) + h4] = make_float4(rtf(co.x * q2.x), rtf(co.y * q2.y),
                                        rtf(co.z * q2.z), rtf(co.w * q2.w));
}

// ---------------------------------------------------------------------------
extern "C" void kernel_launch(void* const* d_in, const int* in_sizes, int n_in,
                              void* d_out, int out_size)
{
    const int*   q       = (const int*)  d_in[0];
    const int*   c       = (const int*)  d_in[1];
    const float* emb     = (const float*)d_in[2];
    const float* Wih_q   = (const float*)d_in[3];
    const float* Whh_q   = (const float*)d_in[4];
    const float* b_q     = (const float*)d_in[5];
    const float* Wih_c   = (const float*)d_in[6];
    const float* Whh_c   = (const float*)d_in[7];
    const float* b_c     = (const float*)d_in[8];
    const float* Wih_m   = (const float*)d_in[9];
    const float* Whh_m   = (const float*)d_in[10];
    const float* b_m     = (const float*)d_in[11];
    const float* sim_w   = (const float*)d_in[12];
    const float* sim_b   = (const float*)d_in[13];
    const float* start_w = (const float*)d_in[14];
    const float* start_b = (const float*)d_in[15];
    const float* end_w   = (const float*)d_in[16];
    const float* end_b   = (const float*)d_in[17];
    float* out = (float*)d_out;

    float *qemb, *cemb, *xw, *xwq, *qout, *cout, *S, *smax, *batt, *cw, *qw, *c2q, *q2c, *G, *M, *wcvt;
    cudaGetSymbolAddress((void**)&qemb, g_qemb);
    cudaGetSymbolAddress((void**)&cemb, g_cemb);
    cudaGetSymbolAddress((void**)&xw,   g_xw);
    cudaGetSymbolAddress((void**)&xwq,  g_xwq);
    cudaGetSymbolAddress((void**)&qout, g_qout);
    cudaGetSymbolAddress((void**)&cout, g_cout);
    cudaGetSymbolAddress((void**)&S,    g_S);
    cudaGetSymbolAddress((void**)&smax, g_smax);
    cudaGetSymbolAddress((void**)&batt, g_batt);
    cudaGetSymbolAddress((void**)&cw,   g_cw);
    cudaGetSymbolAddress((void**)&qw,   g_qw);
    cudaGetSymbolAddress((void**)&c2q,  g_c2q);
    cudaGetSymbolAddress((void**)&q2c,  g_q2c);
    cudaGetSymbolAddress((void**)&G,    g_G);
    cudaGetSymbolAddress((void**)&M,    g_M);
    cudaGetSymbolAddress((void**)&wcvt, g_wcvt);

    cudaFuncSetAttribute(lstm_scan2, cudaFuncAttributeMaxDynamicSharedMemorySize, SCAN_SMEM);
    cudaFuncSetAttribute(gemm_tf32, cudaFuncAttributeMaxDynamicSharedMemorySize, GEMM_SMEM);

    gather_emb<<<(BB * LQ * EE + 255) / 256, 256>>>(q, emb, qemb, BB * LQ * EE);
    gather_emb<<<(BB * LC * EE + 255) / 256, 256>>>(c, emb, cemb, BB * LC * EE);

    cvt_tf32<<<(2 * G4 * EE + 255) / 256, 256>>>(Wih_q, wcvt, 2 * G4 * EE);
    for (int d = 0; d < 2; ++d)
        gemm_tf32<<<dim3(G4 / 128, (BB * LQ) / 128), 128, GEMM_SMEM>>>(
            qemb, wcvt + (size_t)d * G4 * EE, b_q + (size_t)d * G4,
            xwq + (size_t)d * BB * LQ * G4, BB * LQ, G4, EE);
    cvt_tf32<<<(2 * G4 * EE + 255) / 256, 256>>>(Wih_c, wcvt + (size_t)G4 * H8, 2 * G4 * EE);
    for (int d = 0; d < 2; ++d)
        gemm_tf32<<<dim3(G4 / 128, (BB * LC) / 128), 128, GEMM_SMEM>>>(
            cemb, wcvt + (size_t)G4 * H8 + (size_t)d * G4 * EE, b_c + (size_t)d * G4,
            xw + (size_t)d * BB * LC * G4, BB * LC, G4, EE);
    lstm_scan2<<<128, 256, SCAN_SMEM>>>(xw, Whh_c, cout, LC,
                                        xwq, Whh_q, qout, LQ);

    rowdot<<<(BB * LC) / 8, 256>>>(cout, sim_w, nullptr, cw, BB * LC);
    rowdot<<<(BB * LQ) / 8, 256>>>(qout, sim_w + H2, nullptr, qw, BB * LQ);
    attn_S<<<dim3(LC / 64, BB), 256>>>(cout, qout, sim_w, sim_b, cw, qw, S);
    softmax64<<<(BB * LC) / 8, 256>>>(S, smax, BB * LC);
    softmax512<<<BB, 512>>>(smax, batt);
    attn_c2q<<<dim3(H2 / 64, LC / 64, BB), 256>>>(S, qout, c2q);
    attn_q2c<<<dim3(H2 / 128, BB), 128>>>(batt, cout, q2c);
    build_G<<<(int)(((size_t)BB * LC * (H2 / 4) + 255) / 256), 256>>>(cout, c2q, q2c, G);

    cvt_tf32<<<(2 * G4 * H8 + 255) / 256, 256>>>(Wih_m, wcvt, 2 * G4 * H8);
    for (int d = 0; d < 2; ++d)
        gemm_tf32<<<dim3(G4 / 128, (BB * LC) / 128), 128, GEMM_SMEM>>>(
            G, wcvt + (size_t)d * G4 * H8, b_m + (size_t)d * G4,
            xw + (size_t)d * BB * LC * G4, BB * LC, G4, H8);
    lstm_scan2<<<64, 256, SCAN_SMEM>>>(xw, Whh_m, M, LC, xw, Whh_m, M, LC);

    rowdot2<<<(BB * LC) / 8, 256>>>(M, start_w, start_b, end_w, end_b,
                                    out, out + (size_t)BB * LC, BB * LC);
}